// round 3
// baseline (speedup 1.0000x reference)
#include <cuda_runtime.h>

// Problem constants (fixed by dataset): B=1024, S=40*40=1600, V=32
#define SEQL  1600
#define VOC   32
#define GRIDW 40
#define NW    50          // 1600 bits / 32
#define BMAX  2048
#define NWARP 8           // 256 threads
#define TROW  9           // float4 per token row in staging (8 data + 1 pad)

// -------- device scratch (no allocations allowed) --------
__device__ int   g_is64;
__device__ int   g_done;
__device__ float g_bloss[BMAX];

// ---------------------------------------------------------------------------
// Kernel 0: detect labels dtype (int64 vs int32) + reset completion ticket.
// Under int64, every odd 32-bit word (high half of small nonneg value) is 0.
// ---------------------------------------------------------------------------
__global__ void k_init(const unsigned* __restrict__ lw)
{
    __shared__ unsigned r[256];
    unsigned acc = 0;
    for (int i = 2 * threadIdx.x + 1; i < 2 * SEQL; i += 512)
        acc |= lw[i];
    r[threadIdx.x] = acc;
    __syncthreads();
    for (int o = 128; o > 0; o >>= 1) {
        if (threadIdx.x < o) r[threadIdx.x] |= r[threadIdx.x + o];
        __syncthreads();
    }
    if (threadIdx.x == 0) { g_is64 = (r[0] == 0u) ? 1 : 0; g_done = 0; }
}

// ---------------------------------------------------------------------------
// union-find helpers (single-thread, shared-memory parent array)
// ---------------------------------------------------------------------------
__device__ __forceinline__ int uf_find(unsigned short* p, int x)
{
    while (p[x] != x) { p[x] = p[p[x]]; x = p[x]; }   // path halving
    return x;
}

// ---------------------------------------------------------------------------
// Kernel 1: fully fused, one block per batch row.
//  CE pass: coalesced LDG -> warp-private padded smem tile -> token-major LDS.
//  Penalties: spatial via bit-walk (tid<NW), connectivity via single-thread
//  union-find over ~50 set cells. Last block reduces all batches -> out[0].
// ---------------------------------------------------------------------------
__global__ void __launch_bounds__(256) k_main(const float* __restrict__ logits,
                                              const void*  __restrict__ labels,
                                              const float* __restrict__ qh,
                                              float* __restrict__ out, int B)
{
    const int b   = blockIdx.x;
    const int tid = threadIdx.x;
    const int w   = tid >> 5;
    const int l   = tid & 31;
    const int is64 = g_is64;

    __shared__ float4   stage[NWARP * 32 * TROW];   // 36864 B
    __shared__ unsigned spath[NW];
    __shared__ unsigned short par[SEQL];            // union-find parents
    __shared__ float rf[256];
    __shared__ int   ra[256];
    __shared__ int   rb[256];
    __shared__ float s_ce;
    __shared__ int   s_corr, s_cnt, s_comp, s_islast;

    // ---------------- CE streaming pass ----------------
    float ce = 0.f;
    int corr = 0, cnt = 0;
    const float4* gbase = (const float4*)(logits + (size_t)b * SEQL * VOC);
    float4* st = &stage[w * 32 * TROW];

    #pragma unroll 1
    for (int i = 0; i < 7; i++) {
        const int tbase = i * 256 + w * 32;
        if (tbase < SEQL) {
            // coalesced global load (8x 512B contiguous per warp), stage to smem
            const float4* src = gbase + (size_t)tbase * 8;
            #pragma unroll
            for (int k = 0; k < 8; k++) {
                float4 v = __ldg(src + k * 32 + l);
                int f = k * 32 + l;                 // float4 index in chunk
                st[(f >> 3) * TROW + (f & 7)] = v;
            }
            __syncwarp();

            // per-lane token compute (token-major smem reads)
            const int s = tbase + l;
            long long lb = is64 ? ((const long long*)labels)[(size_t)b * SEQL + s]
                                : (long long)((const int*)labels)[(size_t)b * SEQL + s];
            const bool msk = (lb != -100);
            const int  sl  = ((unsigned long long)lb < VOC) ? (int)lb : 0;
            const int  qsel = sl >> 2, rsel = sl & 3;

            const float4* row = st + l * TROW;
            float ma = -1e30f, mb = -1e30f;
            float s0 = 0.f, s1 = 0.f;
            float x6 = 0.f;
            float4 vs = row[0];
            #pragma unroll
            for (int q = 0; q < 8; q++) {
                float4 v = row[q];
                if (q == qsel) vs = v;
                if (q == 1)    x6 = v.z;            // index 6 = float4 1, comp z
                ma = fmaxf(ma, fmaxf(v.x, v.y));
                mb = fmaxf(mb, fmaxf(v.z, v.w));
                s0 += __expf(v.x) + __expf(v.y);
                s1 += __expf(v.z) + __expf(v.w);
            }
            const float m  = fmaxf(ma, mb);
            const float xl = (rsel & 2) ? ((rsel & 1) ? vs.w : vs.z)
                                        : ((rsel & 1) ? vs.y : vs.x);
            if (msk) {
                ce += __logf(s0 + s1) - xl;         // == m + log(sum exp(x-m)) - xl
                cnt++;
                corr += (xl == m) ? 1 : 0;          // pred == label (unique max)
            }
            unsigned bal = __ballot_sync(0xffffffffu, x6 == m);
            if (l == 0) spath[tbase >> 5] = bal;    // tbase is 32-aligned
            __syncwarp();                           // stage reuse next iter
        }
    }

    rf[tid] = ce; ra[tid] = corr; rb[tid] = cnt;
    __syncthreads();
    for (int o = 128; o > 0; o >>= 1) {
        if (tid < o) { rf[tid] += rf[tid+o]; ra[tid] += ra[tid+o]; rb[tid] += rb[tid+o]; }
        __syncthreads();
    }
    if (tid == 0) { s_ce = rf[0]; s_corr = ra[0]; s_cnt = rb[0]; }
    __syncthreads();   // spath fully visible to all

    // ---------------- spatial penalty (tid < NW) ----------------
    float spen = 0.f;
    rf[tid] = 0.f;
    if (tid < NW) {
        unsigned ww = spath[tid];
        while (ww) {
            int bit = __ffs(ww) - 1;
            ww &= ww - 1;
            int i = tid * 32 + bit;
            int j = -1;
            if (ww) {
                j = tid * 32 + __ffs(ww) - 1;
            } else {
                for (int w2 = tid + 1; w2 < NW; w2++) {
                    unsigned vv = spath[w2];
                    if (vv) { j = w2 * 32 + __ffs(vv) - 1; break; }
                }
            }
            if (j >= 0) {
                int d = abs(i / GRIDW - j / GRIDW) + abs(i % GRIDW - j % GRIDW);
                if (d > 1) spen += (float)(d - 1) * 10.0f;
            }
        }
        rf[tid] = spen;
    }

    // ---------------- connectivity: single-thread union-find (tid==64) ------
    // runs concurrently with spatial warps above (disjoint threads, spath RO)
    if (tid == 64) {
        // init parents of set cells
        for (int wd = 0; wd < NW; wd++) {
            unsigned v = spath[wd];
            while (v) {
                int i = wd * 32 + (__ffs(v) - 1);
                v &= v - 1;
                par[i] = (unsigned short)i;
            }
        }
        // union with left/up neighbors
        for (int wd = 0; wd < NW; wd++) {
            unsigned v = spath[wd];
            while (v) {
                int i = wd * 32 + (__ffs(v) - 1);
                v &= v - 1;
                int c = i % GRIDW;
                if (c > 0 && ((spath[(i-1) >> 5] >> ((i-1) & 31)) & 1u)) {
                    int ra_ = uf_find(par, i), rb_ = uf_find(par, i - 1);
                    if (ra_ != rb_) par[max(ra_, rb_)] = (unsigned short)min(ra_, rb_);
                }
                if (i >= GRIDW && ((spath[(i-GRIDW) >> 5] >> ((i-GRIDW) & 31)) & 1u)) {
                    int ra_ = uf_find(par, i), rb_ = uf_find(par, i - GRIDW);
                    if (ra_ != rb_) par[max(ra_, rb_)] = (unsigned short)min(ra_, rb_);
                }
            }
        }
        // count roots
        int comp = 0;
        for (int wd = 0; wd < NW; wd++) {
            unsigned v = spath[wd];
            while (v) {
                int i = wd * 32 + (__ffs(v) - 1);
                v &= v - 1;
                if (par[i] == (unsigned short)i) comp++;
            }
        }
        s_comp = comp;
    }
    __syncthreads();

    for (int o = 128; o > 0; o >>= 1) {
        if (tid < o) rf[tid] += rf[tid + o];
        __syncthreads();
    }

    // ---------------- per-batch loss + ticket ----------------
    if (tid == 0) {
        int comp = s_comp;
        float conn = (comp > 1) ? (float)(comp - 1) * 5.0f : 0.f;
        float divi = (float)max(s_cnt, 1);
        float lm   = s_ce / divi;
        float t    = (s_corr == s_cnt) ? 1.f : 0.f;
        float x    = qh[b];
        float bce  = fmaxf(x, 0.f) - x * t + log1pf(expf(-fabsf(x)));
        g_bloss[b] = lm + 0.5f * bce + (rf[0] + conn) / (float)B;
        __threadfence();
        int tk = atomicAdd(&g_done, 1);
        s_islast = (tk == gridDim.x - 1) ? 1 : 0;
    }
    __syncthreads();

    // ---------------- last block: deterministic final reduction -------------
    if (s_islast) {
        __threadfence();
        __shared__ double rd[256];
        double a = 0.0;
        for (int i = tid; i < B; i += 256) a += (double)g_bloss[i];
        rd[tid] = a;
        __syncthreads();
        for (int o = 128; o > 0; o >>= 1) {
            if (tid < o) rd[tid] += rd[tid + o];
            __syncthreads();
        }
        if (tid == 0) out[0] = (float)rd[0];
    }
}

// ---------------------------------------------------------------------------
extern "C" void kernel_launch(void* const* d_in, const int* in_sizes, int n_in,
                              void* d_out, int out_size)
{
    const float* logits = (const float*)d_in[0];
    const void*  labels = d_in[1];
    const float* qh     = (const float*)d_in[2];
    // d_in[3]=halted, d_in[4]=steps: metrics-only in reference, unused.

    int B = in_sizes[2];
    if (B > BMAX) B = BMAX;        // dataset uses B=1024

    k_init<<<1, 256>>>((const unsigned*)labels);
    k_main<<<B, 256>>>(logits, labels, qh, (float*)d_out, B);
}

// round 4
// speedup vs baseline: 1.1990x; 1.1990x over previous
#include <cuda_runtime.h>

// Problem constants (fixed by dataset): B=1024, S=40*40=1600, V=32
#define SEQL  1600
#define VOC   32
#define GRIDW 40
#define NW    50          // 1600 bits / 32
#define BMAX  2048

// -------- device scratch (no allocations allowed) --------
__device__ int   g_is64;
__device__ int   g_done;
__device__ float g_bloss[BMAX];

// ---------------------------------------------------------------------------
// Kernel 0: detect labels dtype (int64 vs int32) + reset completion ticket.
// Under int64, every odd 32-bit word (high half of small nonneg value) is 0.
// ---------------------------------------------------------------------------
__global__ void k_init(const unsigned* __restrict__ lw)
{
    __shared__ unsigned r[256];
    unsigned acc = 0;
    for (int i = 2 * threadIdx.x + 1; i < 2 * SEQL; i += 512)
        acc |= lw[i];
    r[threadIdx.x] = acc;
    __syncthreads();
    for (int o = 128; o > 0; o >>= 1) {
        if (threadIdx.x < o) r[threadIdx.x] |= r[threadIdx.x + o];
        __syncthreads();
    }
    if (threadIdx.x == 0) { g_is64 = (r[0] == 0u) ? 1 : 0; g_done = 0; }
}

// ---------------------------------------------------------------------------
__device__ __forceinline__ int uf_find(unsigned short* p, int x)
{
    while (p[x] != x) { p[x] = p[p[x]]; x = p[x]; }   // path halving
    return x;
}

__device__ __forceinline__ float pick(float4 v, int r)
{
    return (r & 2) ? ((r & 1) ? v.w : v.z) : ((r & 1) ? v.y : v.x);
}

// ---------------------------------------------------------------------------
// Kernel 1: fully fused, one block per batch row.
//  CE pass: 8 lanes per token, 2 coalesced LDG.128 per warp-pass (8 tokens),
//  shfl.bfly group reductions; no smem, no syncs in the hot loop.
//  Penalties: spatial bit-walk + single-thread union-find. Last block reduces.
// ---------------------------------------------------------------------------
__global__ void __launch_bounds__(256) k_main(const float* __restrict__ logits,
                                              const void*  __restrict__ labels,
                                              const float* __restrict__ qh,
                                              float* __restrict__ out, int B)
{
    const int b   = blockIdx.x;
    const int tid = threadIdx.x;
    const int w   = tid >> 5;
    const int l   = tid & 31;
    const int g   = l >> 3;        // 4 lane-groups per warp
    const int q   = l & 7;         // float4 slot within a token
    const int is64 = g_is64;

    __shared__ unsigned spath[NW];
    __shared__ unsigned short par[SEQL];
    __shared__ float rf[256];
    __shared__ int   ra[256];
    __shared__ int   rb[256];
    __shared__ float s_ce;
    __shared__ int   s_corr, s_cnt, s_comp, s_islast;

    for (int i = tid; i < NW; i += 256) spath[i] = 0u;
    __syncthreads();

    // ---------------- CE streaming pass ----------------
    float ce = 0.f;
    int corr = 0, cnt = 0;
    const float4*     gbase = (const float4*)(logits + (size_t)b * SEQL * VOC);
    const long long*  L64   = (const long long*)labels;
    const int*        L32   = (const int*)labels;

    #pragma unroll 5
    for (int p = 0; p < 25; p++) {
        const int T = p * 64 + w * 8;             // this warp's 8-token base
        const float4* src = gbase + (size_t)T * 8;
        float4 v1 = __ldg(src + l);               // token T+g,   slot q
        float4 v2 = __ldg(src + 32 + l);          // token T+g+4, slot q
        const int t1 = T + g, t2 = T + g + 4;

        long long lb1 = is64 ? L64[(size_t)b * SEQL + t1]
                             : (long long)L32[(size_t)b * SEQL + t1];
        long long lb2 = is64 ? L64[(size_t)b * SEQL + t2]
                             : (long long)L32[(size_t)b * SEQL + t2];

        float m1 = fmaxf(fmaxf(v1.x, v1.y), fmaxf(v1.z, v1.w));
        float m2 = fmaxf(fmaxf(v2.x, v2.y), fmaxf(v2.z, v2.w));
        float s1 = (__expf(v1.x) + __expf(v1.y)) + (__expf(v1.z) + __expf(v1.w));
        float s2 = (__expf(v2.x) + __expf(v2.y)) + (__expf(v2.z) + __expf(v2.w));

        const int sl1 = ((unsigned long long)lb1 < VOC) ? (int)lb1 : 0;
        const int sl2 = ((unsigned long long)lb2 < VOC) ? (int)lb2 : 0;
        float x1 = (q == (sl1 >> 2)) ? pick(v1, sl1 & 3) : -1e30f;
        float x2 = (q == (sl2 >> 2)) ? pick(v2, sl2 & 3) : -1e30f;

        #pragma unroll
        for (int o = 1; o < 8; o <<= 1) {
            m1 = fmaxf(m1, __shfl_xor_sync(0xffffffffu, m1, o));
            s1 +=          __shfl_xor_sync(0xffffffffu, s1, o);
            x1 = fmaxf(x1, __shfl_xor_sync(0xffffffffu, x1, o));
            m2 = fmaxf(m2, __shfl_xor_sync(0xffffffffu, m2, o));
            s2 +=          __shfl_xor_sync(0xffffffffu, s2, o);
            x2 = fmaxf(x2, __shfl_xor_sync(0xffffffffu, x2, o));
        }

        if (q == 1) {   // this lane's v.z is vocab index 6 (= PATH token)
            if (v1.z == m1) atomicOr(&spath[t1 >> 5], 1u << (t1 & 31));
            if (v2.z == m2) atomicOr(&spath[t2 >> 5], 1u << (t2 & 31));
        }
        if (q == 0) {   // one accumulator lane per token
            if (lb1 != -100) { ce += __logf(s1) - x1; cnt++; corr += (x1 == m1); }
            if (lb2 != -100) { ce += __logf(s2) - x2; cnt++; corr += (x2 == m2); }
        }
    }

    rf[tid] = ce; ra[tid] = corr; rb[tid] = cnt;
    __syncthreads();
    for (int o = 128; o > 0; o >>= 1) {
        if (tid < o) { rf[tid] += rf[tid+o]; ra[tid] += ra[tid+o]; rb[tid] += rb[tid+o]; }
        __syncthreads();
    }
    if (tid == 0) { s_ce = rf[0]; s_corr = ra[0]; s_cnt = rb[0]; }
    __syncthreads();   // spath fully visible

    // ---------------- spatial penalty (tid < NW) ----------------
    rf[tid] = 0.f;
    if (tid < NW) {
        float spen = 0.f;
        unsigned ww = spath[tid];
        while (ww) {
            int bit = __ffs(ww) - 1;
            ww &= ww - 1;
            int i = tid * 32 + bit;
            int j = -1;
            if (ww) {
                j = tid * 32 + __ffs(ww) - 1;
            } else {
                for (int w2 = tid + 1; w2 < NW; w2++) {
                    unsigned vv = spath[w2];
                    if (vv) { j = w2 * 32 + __ffs(vv) - 1; break; }
                }
            }
            if (j >= 0) {
                int d = abs(i / GRIDW - j / GRIDW) + abs(i % GRIDW - j % GRIDW);
                if (d > 1) spen += (float)(d - 1) * 10.0f;
            }
        }
        rf[tid] = spen;
    }

    // ---------------- connectivity: single-thread union-find (tid==64) ------
    if (tid == 64) {
        for (int wd = 0; wd < NW; wd++) {
            unsigned v = spath[wd];
            while (v) {
                int i = wd * 32 + (__ffs(v) - 1);
                v &= v - 1;
                par[i] = (unsigned short)i;
            }
        }
        for (int wd = 0; wd < NW; wd++) {
            unsigned v = spath[wd];
            while (v) {
                int i = wd * 32 + (__ffs(v) - 1);
                v &= v - 1;
                int c = i % GRIDW;
                if (c > 0 && ((spath[(i-1) >> 5] >> ((i-1) & 31)) & 1u)) {
                    int r1 = uf_find(par, i), r2 = uf_find(par, i - 1);
                    if (r1 != r2) par[max(r1, r2)] = (unsigned short)min(r1, r2);
                }
                if (i >= GRIDW && ((spath[(i-GRIDW) >> 5] >> ((i-GRIDW) & 31)) & 1u)) {
                    int r1 = uf_find(par, i), r2 = uf_find(par, i - GRIDW);
                    if (r1 != r2) par[max(r1, r2)] = (unsigned short)min(r1, r2);
                }
            }
        }
        int comp = 0;
        for (int wd = 0; wd < NW; wd++) {
            unsigned v = spath[wd];
            while (v) {
                int i = wd * 32 + (__ffs(v) - 1);
                v &= v - 1;
                if (par[i] == (unsigned short)i) comp++;
            }
        }
        s_comp = comp;
    }
    __syncthreads();

    for (int o = 128; o > 0; o >>= 1) {
        if (tid < o) rf[tid] += rf[tid + o];
        __syncthreads();
    }

    // ---------------- per-batch loss + ticket ----------------
    if (tid == 0) {
        int comp = s_comp;
        float conn = (comp > 1) ? (float)(comp - 1) * 5.0f : 0.f;
        float divi = (float)max(s_cnt, 1);
        float lm   = s_ce / divi;
        float t    = (s_corr == s_cnt) ? 1.f : 0.f;
        float x    = qh[b];
        float bce  = fmaxf(x, 0.f) - x * t + log1pf(expf(-fabsf(x)));
        g_bloss[b] = lm + 0.5f * bce + (rf[0] + conn) / (float)B;
        __threadfence();
        int tk = atomicAdd(&g_done, 1);
        s_islast = (tk == gridDim.x - 1) ? 1 : 0;
    }
    __syncthreads();

    // ---------------- last block: deterministic final reduction -------------
    if (s_islast) {
        __threadfence();
        __shared__ double rd[256];
        double a = 0.0;
        for (int i = tid; i < B; i += 256) a += (double)g_bloss[i];
        rd[tid] = a;
        __syncthreads();
        for (int o = 128; o > 0; o >>= 1) {
            if (tid < o) rd[tid] += rd[tid + o];
            __syncthreads();
        }
        if (tid == 0) out[0] = (float)rd[0];
    }
}

// ---------------------------------------------------------------------------
extern "C" void kernel_launch(void* const* d_in, const int* in_sizes, int n_in,
                              void* d_out, int out_size)
{
    const float* logits = (const float*)d_in[0];
    const void*  labels = d_in[1];
    const float* qh     = (const float*)d_in[2];
    // d_in[3]=halted, d_in[4]=steps: metrics-only in reference, unused.

    int B = in_sizes[2];
    if (B > BMAX) B = BMAX;        // dataset uses B=1024

    k_init<<<1, 256>>>((const unsigned*)labels);
    k_main<<<B, 256>>>(logits, labels, qh, (float*)d_out, B);
}